// round 1
// baseline (speedup 1.0000x reference)
#include <cuda_runtime.h>

#define THREADS 128

// ---- shared-memory layout (floats) ----
#define S_W1T   0        // [105][64]  bw1 transposed  (6720)
#define S_B1    6720     // [64]
#define S_W2T   6784     // [64][32]   bw2 transposed  (2048)
#define S_B2    8832     // [32]
#define S_V1T   8864     // [32][32]   vw1 transposed, pre-scaled by 1/3 (1024)
#define S_VB1   9888     // [32]
#define S_V2T   9920     // [32][32]   vw2 transposed (1024)
#define S_VB2   10944    // [32]
#define S_R1T   10976    // [96][32]   rw1 transposed (3072)
#define S_RB1   14048    // [32]
#define S_R2T   14080    // [32][16]   rw2 transposed (512)
#define S_RB2   14592    // [16]
#define S_RW3   14608    // [3][16]    rw3 as-is (48)
#define S_RB3   14656    // [4]
#define S_TOT   14660
#define SMEM_BYTES (S_TOT * 4)

__device__ __forceinline__ float elu1(float x) {
    return x > 0.f ? x : (__expf(x) - 1.f);
}

__global__ __launch_bounds__(THREADS, 2)
void nerf_rgb_head_kernel(
    const float* __restrict__ rgb,
    const float* __restrict__ bw1, const float* __restrict__ bb1,
    const float* __restrict__ bw2, const float* __restrict__ bb2,
    const float* __restrict__ vw1, const float* __restrict__ vb1,
    const float* __restrict__ vw2, const float* __restrict__ vb2,
    const float* __restrict__ rw1, const float* __restrict__ rb1,
    const float* __restrict__ rw2, const float* __restrict__ rb2,
    const float* __restrict__ rw3, const float* __restrict__ rb3,
    float* __restrict__ out_in,   // P*3*3 : rgb_feat[...,:3]
    float* __restrict__ out_rgb,  // P*3
    int P)
{
    extern __shared__ float s[];
    const int tid = threadIdx.x;

    // ---- stage weights into SMEM (transposed so inner dim = output neuron) ----
    for (int i = tid; i < 6720; i += THREADS) { int k = i >> 6, j = i & 63; s[S_W1T + i] = bw1[j * 105 + k]; }
    for (int i = tid; i < 64;   i += THREADS) s[S_B1 + i] = bb1[i];
    for (int i = tid; i < 2048; i += THREADS) { int k = i >> 5, j = i & 31; s[S_W2T + i] = bw2[j * 64 + k]; }
    for (int i = tid; i < 32;   i += THREADS) s[S_B2 + i] = bb2[i];
    for (int i = tid; i < 1024; i += THREADS) { int k = i >> 5, j = i & 31; s[S_V1T + i] = vw1[j * 32 + k] * (1.f / 3.f); }
    for (int i = tid; i < 32;   i += THREADS) s[S_VB1 + i] = vb1[i];
    for (int i = tid; i < 1024; i += THREADS) { int k = i >> 5, j = i & 31; s[S_V2T + i] = vw2[j * 32 + k]; }
    for (int i = tid; i < 32;   i += THREADS) s[S_VB2 + i] = vb2[i];
    for (int i = tid; i < 3072; i += THREADS) { int k = i >> 5, j = i & 31; s[S_R1T + i] = rw1[j * 96 + k]; }
    for (int i = tid; i < 32;   i += THREADS) s[S_RB1 + i] = rb1[i];
    for (int i = tid; i < 512;  i += THREADS) { int k = i >> 4, j = i & 15; s[S_R2T + i] = rw2[j * 32 + k]; }
    for (int i = tid; i < 16;   i += THREADS) s[S_RB2 + i] = rb2[i];
    for (int i = tid; i < 48;   i += THREADS) s[S_RW3 + i] = rw3[i];
    for (int i = tid; i < 4;    i += THREADS) s[S_RB3 + i] = (i < 3) ? rb3[i] : 0.f;
    __syncthreads();

    const int p = blockIdx.x * THREADS + tid;
    if (p >= P) return;

    const float* fbase = rgb + (size_t)p * 105;

    // ---- pass 1: per-feature mean/var over views + rgb_in copy ----
    float sm[35], sq[35];
#pragma unroll
    for (int k = 0; k < 35; ++k) { sm[k] = 0.f; sq[k] = 0.f; }
#pragma unroll
    for (int v = 0; v < 3; ++v) {
#pragma unroll
        for (int k = 0; k < 35; ++k) {
            float t = fbase[v * 35 + k];
            sm[k] += t;
            sq[k] = fmaf(t, t, sq[k]);
            if (k < 3) out_in[((size_t)p * 3 + v) * 3 + k] = t;
        }
    }
    // coefficients [mean(35), var(35)] -> local array (read with dynamic index)
    float coef_l[70];
#pragma unroll
    for (int k = 0; k < 35; ++k) {
        float m = sm[k] * (1.f / 3.f);
        coef_l[k] = m;
        coef_l[35 + k] = fmaf(-m, m, sq[k] * (1.f / 3.f));
    }

    // ---- g1 = bb1 + W1[:, :70] @ [mean, var]  (shared across views) ----
    float g1[64];
#pragma unroll
    for (int j = 0; j < 16; ++j) {
        float4 b = reinterpret_cast<const float4*>(s + S_B1)[j];
        g1[4 * j] = b.x; g1[4 * j + 1] = b.y; g1[4 * j + 2] = b.z; g1[4 * j + 3] = b.w;
    }
#pragma unroll 1
    for (int k = 0; k < 70; ++k) {
        float c = coef_l[k];
        const float4* w = reinterpret_cast<const float4*>(s + S_W1T + k * 64);
#pragma unroll
        for (int j = 0; j < 16; ++j) {
            float4 ww = w[j];
            g1[4 * j]     = fmaf(c, ww.x, g1[4 * j]);
            g1[4 * j + 1] = fmaf(c, ww.y, g1[4 * j + 1]);
            g1[4 * j + 2] = fmaf(c, ww.z, g1[4 * j + 2]);
            g1[4 * j + 3] = fmaf(c, ww.w, g1[4 * j + 3]);
        }
    }

    // ---- r1 accumulator (final 96->32 layer, accumulated per view) ----
    float r1[32];
#pragma unroll
    for (int j = 0; j < 8; ++j) {
        float4 b = reinterpret_cast<const float4*>(s + S_RB1)[j];
        r1[4 * j] = b.x; r1[4 * j + 1] = b.y; r1[4 * j + 2] = b.z; r1[4 * j + 3] = b.w;
    }

    // ---- per-view MLP ----
#pragma unroll 1
    for (int v = 0; v < 3; ++v) {
        const float* fv = fbase + v * 35;

        // h1 = elu(g1 + W1[:, 70:105] @ f_v)
        float h1[64];
#pragma unroll
        for (int j = 0; j < 64; ++j) h1[j] = g1[j];
#pragma unroll 1
        for (int k = 0; k < 35; ++k) {
            float c = fv[k];
            const float4* w = reinterpret_cast<const float4*>(s + S_W1T + (70 + k) * 64);
#pragma unroll
            for (int j = 0; j < 16; ++j) {
                float4 ww = w[j];
                h1[4 * j]     = fmaf(c, ww.x, h1[4 * j]);
                h1[4 * j + 1] = fmaf(c, ww.y, h1[4 * j + 1]);
                h1[4 * j + 2] = fmaf(c, ww.z, h1[4 * j + 2]);
                h1[4 * j + 3] = fmaf(c, ww.w, h1[4 * j + 3]);
            }
        }
        float h1l[64];   // local: consumed with dynamic index below
#pragma unroll
        for (int j = 0; j < 64; ++j) h1l[j] = elu1(h1[j]);

        // h2 = elu(bb2 + W2 @ h1)
        float h2[32];
#pragma unroll
        for (int j = 0; j < 8; ++j) {
            float4 b = reinterpret_cast<const float4*>(s + S_B2)[j];
            h2[4 * j] = b.x; h2[4 * j + 1] = b.y; h2[4 * j + 2] = b.z; h2[4 * j + 3] = b.w;
        }
#pragma unroll 1
        for (int k = 0; k < 64; ++k) {
            float c = h1l[k];
            const float4* w = reinterpret_cast<const float4*>(s + S_W2T + k * 32);
#pragma unroll
            for (int j = 0; j < 8; ++j) {
                float4 ww = w[j];
                h2[4 * j]     = fmaf(c, ww.x, h2[4 * j]);
                h2[4 * j + 1] = fmaf(c, ww.y, h2[4 * j + 1]);
                h2[4 * j + 2] = fmaf(c, ww.z, h2[4 * j + 2]);
                h2[4 * j + 3] = fmaf(c, ww.w, h2[4 * j + 3]);
            }
        }
        float h2l[32];
#pragma unroll
        for (int j = 0; j < 32; ++j) h2l[j] = elu1(h2[j]);

        // t1 = elu(vb1 + (vw1/3) @ h2)   [x/num_views folded into weights]
        float t1[32];
#pragma unroll
        for (int j = 0; j < 8; ++j) {
            float4 b = reinterpret_cast<const float4*>(s + S_VB1)[j];
            t1[4 * j] = b.x; t1[4 * j + 1] = b.y; t1[4 * j + 2] = b.z; t1[4 * j + 3] = b.w;
        }
#pragma unroll 1
        for (int k = 0; k < 32; ++k) {
            float c = h2l[k];
            const float4* w = reinterpret_cast<const float4*>(s + S_V1T + k * 32);
#pragma unroll
            for (int j = 0; j < 8; ++j) {
                float4 ww = w[j];
                t1[4 * j]     = fmaf(c, ww.x, t1[4 * j]);
                t1[4 * j + 1] = fmaf(c, ww.y, t1[4 * j + 1]);
                t1[4 * j + 2] = fmaf(c, ww.z, t1[4 * j + 2]);
                t1[4 * j + 3] = fmaf(c, ww.w, t1[4 * j + 3]);
            }
        }
        float t1l[32];
#pragma unroll
        for (int j = 0; j < 32; ++j) t1l[j] = elu1(t1[j]);

        // t2 = elu(vb2 + vw2 @ t1) ; x = h2 + t2
        float t2[32];
#pragma unroll
        for (int j = 0; j < 8; ++j) {
            float4 b = reinterpret_cast<const float4*>(s + S_VB2)[j];
            t2[4 * j] = b.x; t2[4 * j + 1] = b.y; t2[4 * j + 2] = b.z; t2[4 * j + 3] = b.w;
        }
#pragma unroll 1
        for (int k = 0; k < 32; ++k) {
            float c = t1l[k];
            const float4* w = reinterpret_cast<const float4*>(s + S_V2T + k * 32);
#pragma unroll
            for (int j = 0; j < 8; ++j) {
                float4 ww = w[j];
                t2[4 * j]     = fmaf(c, ww.x, t2[4 * j]);
                t2[4 * j + 1] = fmaf(c, ww.y, t2[4 * j + 1]);
                t2[4 * j + 2] = fmaf(c, ww.z, t2[4 * j + 2]);
                t2[4 * j + 3] = fmaf(c, ww.w, t2[4 * j + 3]);
            }
        }
        float xl[32];
#pragma unroll
        for (int j = 0; j < 32; ++j) xl[j] = h2l[j] + elu1(t2[j]);

        // r1 += rw1[:, v*32 : v*32+32] @ x
#pragma unroll 1
        for (int k = 0; k < 32; ++k) {
            float c = xl[k];
            const float4* w = reinterpret_cast<const float4*>(s + S_R1T + (v * 32 + k) * 32);
#pragma unroll
            for (int j = 0; j < 8; ++j) {
                float4 ww = w[j];
                r1[4 * j]     = fmaf(c, ww.x, r1[4 * j]);
                r1[4 * j + 1] = fmaf(c, ww.y, r1[4 * j + 1]);
                r1[4 * j + 2] = fmaf(c, ww.z, r1[4 * j + 2]);
                r1[4 * j + 3] = fmaf(c, ww.w, r1[4 * j + 3]);
            }
        }
    }

    // ---- head: elu(r1) -> 16 -> elu -> 3 -> sigmoid ----
    float r1l[32];
#pragma unroll
    for (int j = 0; j < 32; ++j) r1l[j] = elu1(r1[j]);

    float r2[16];
#pragma unroll
    for (int j = 0; j < 4; ++j) {
        float4 b = reinterpret_cast<const float4*>(s + S_RB2)[j];
        r2[4 * j] = b.x; r2[4 * j + 1] = b.y; r2[4 * j + 2] = b.z; r2[4 * j + 3] = b.w;
    }
#pragma unroll 1
    for (int k = 0; k < 32; ++k) {
        float c = r1l[k];
        const float4* w = reinterpret_cast<const float4*>(s + S_R2T + k * 16);
#pragma unroll
        for (int j = 0; j < 4; ++j) {
            float4 ww = w[j];
            r2[4 * j]     = fmaf(c, ww.x, r2[4 * j]);
            r2[4 * j + 1] = fmaf(c, ww.y, r2[4 * j + 1]);
            r2[4 * j + 2] = fmaf(c, ww.z, r2[4 * j + 2]);
            r2[4 * j + 3] = fmaf(c, ww.w, r2[4 * j + 3]);
        }
    }
    float r2e[16];
#pragma unroll
    for (int j = 0; j < 16; ++j) r2e[j] = elu1(r2[j]);

#pragma unroll
    for (int c = 0; c < 3; ++c) {
        float a = s[S_RB3 + c];
#pragma unroll
        for (int k = 0; k < 16; ++k)
            a = fmaf(r2e[k], s[S_RW3 + c * 16 + k], a);
        out_rgb[(size_t)p * 3 + c] = 1.f / (1.f + __expf(-a));
    }
}

extern "C" void kernel_launch(void* const* d_in, const int* in_sizes, int n_in,
                              void* d_out, int out_size)
{
    const float* rgb = (const float*)d_in[0];
    const float* bw1 = (const float*)d_in[1];
    const float* bb1 = (const float*)d_in[2];
    const float* bw2 = (const float*)d_in[3];
    const float* bb2 = (const float*)d_in[4];
    const float* vw1 = (const float*)d_in[5];
    const float* vb1 = (const float*)d_in[6];
    const float* vw2 = (const float*)d_in[7];
    const float* vb2 = (const float*)d_in[8];
    const float* rw1 = (const float*)d_in[9];
    const float* rb1 = (const float*)d_in[10];
    const float* rw2 = (const float*)d_in[11];
    const float* rb2 = (const float*)d_in[12];
    const float* rw3 = (const float*)d_in[13];
    const float* rb3 = (const float*)d_in[14];

    const int P = in_sizes[0] / 105;      // 524288 points
    float* out_in  = (float*)d_out;       // rgb_in : P*9 floats
    float* out_rgb = (float*)d_out + (size_t)P * 9;  // rgb_out : P*3 floats

    cudaFuncSetAttribute(nerf_rgb_head_kernel,
                         cudaFuncAttributeMaxDynamicSharedMemorySize, SMEM_BYTES);

    const int blocks = (P + THREADS - 1) / THREADS;
    nerf_rgb_head_kernel<<<blocks, THREADS, SMEM_BYTES>>>(
        rgb, bw1, bb1, bw2, bb2, vw1, vb1, vw2, vb2,
        rw1, rb1, rw2, rb2, rw3, rb3, out_in, out_rgb, P);
}

// round 3
// speedup vs baseline: 1.3930x; 1.3930x over previous
#include <cuda_runtime.h>

#define THREADS 128

// ---- shared-memory layout (floats) ----
#define S_W1T   0        // [105][64]  bw1 transposed  (6720)
#define S_B1    6720     // [64]
#define S_W2T   6784     // [64][32]   bw2 transposed  (2048)
#define S_B2    8832     // [32]
#define S_V1T   8864     // [32][32]   vw1 transposed, pre-scaled by 1/3 (1024)
#define S_VB1   9888     // [32]
#define S_V2T   9920     // [32][32]   vw2 transposed (1024)
#define S_VB2   10944    // [32]
#define S_R1T   10976    // [96][32]   rw1 transposed (3072)
#define S_RB1   14048    // [32]
#define S_R2T   14080    // [32][16]   rw2 transposed (512)
#define S_RB2   14592    // [16]
#define S_RW3   14608    // [3][16]    rw3 as-is (48)
#define S_RB3   14656    // [4]
#define S_TOT   14660
#define SMEM_BYTES (S_TOT * 4)

typedef unsigned long long ull;

__device__ __forceinline__ float elu1(float x) {
    return x > 0.f ? x : (__expf(x) - 1.f);
}

// packed fp32x2 FMA: d = a*b + d   (sm_103a FFMA2, PTX-only)
__device__ __forceinline__ void ffma2(ull &d, ull a, ull b) {
    asm("fma.rn.f32x2 %0, %1, %2, %0;" : "+l"(d) : "l"(a), "l"(b));
}
__device__ __forceinline__ ull bcast2(float c) {
    ull v; asm("mov.b64 %0, {%1, %2};" : "=l"(v) : "f"(c), "f"(c)); return v;
}
__device__ __forceinline__ ull pack2(float lo, float hi) {
    ull v; asm("mov.b64 %0, {%1, %2};" : "=l"(v) : "f"(lo), "f"(hi)); return v;
}
__device__ __forceinline__ void unpack2(ull v, float &lo, float &hi) {
    asm("mov.b64 {%0, %1}, %2;" : "=f"(lo), "=f"(hi) : "l"(v));
}

// acc[OUT/2] += c2 (*) row[0..OUT)   — row is SMEM, 16B-aligned
template<int OUT>
__device__ __forceinline__ void fma_row(ull* acc, const float* row, ull c2) {
    const ulonglong2* wp = reinterpret_cast<const ulonglong2*>(row);
#pragma unroll
    for (int q = 0; q < OUT / 4; ++q) {
        ulonglong2 w = wp[q];
        ffma2(acc[2 * q],     c2, w.x);
        ffma2(acc[2 * q + 1], c2, w.y);
    }
}

template<int OUT>
__device__ __forceinline__ void load_bias(ull* acc, const float* b) {
    const ulonglong2* bp = reinterpret_cast<const ulonglong2*>(b);
#pragma unroll
    for (int q = 0; q < OUT / 4; ++q) {
        ulonglong2 w = bp[q];
        acc[2 * q]     = w.x;
        acc[2 * q + 1] = w.y;
    }
}

__global__ __launch_bounds__(THREADS, 2)
void nerf_rgb_head_kernel(
    const float* __restrict__ rgb,
    const float* __restrict__ bw1, const float* __restrict__ bb1,
    const float* __restrict__ bw2, const float* __restrict__ bb2,
    const float* __restrict__ vw1, const float* __restrict__ vb1,
    const float* __restrict__ vw2, const float* __restrict__ vb2,
    const float* __restrict__ rw1, const float* __restrict__ rb1,
    const float* __restrict__ rw2, const float* __restrict__ rb2,
    const float* __restrict__ rw3, const float* __restrict__ rb3,
    float* __restrict__ out_in,   // P*9 : rgb_feat[...,:3]
    float* __restrict__ out_rgb,  // P*3
    int P)
{
    extern __shared__ float s[];
    const int tid = threadIdx.x;

    // ---- stage weights into SMEM (transposed: inner dim = output neuron) ----
    for (int i = tid; i < 6720; i += THREADS) { int k = i >> 6, j = i & 63; s[S_W1T + i] = bw1[j * 105 + k]; }
    for (int i = tid; i < 64;   i += THREADS) s[S_B1 + i] = bb1[i];
    for (int i = tid; i < 2048; i += THREADS) { int k = i >> 5, j = i & 31; s[S_W2T + i] = bw2[j * 64 + k]; }
    for (int i = tid; i < 32;   i += THREADS) s[S_B2 + i] = bb2[i];
    for (int i = tid; i < 1024; i += THREADS) { int k = i >> 5, j = i & 31; s[S_V1T + i] = vw1[j * 32 + k] * (1.f / 3.f); }
    for (int i = tid; i < 32;   i += THREADS) s[S_VB1 + i] = vb1[i];
    for (int i = tid; i < 1024; i += THREADS) { int k = i >> 5, j = i & 31; s[S_V2T + i] = vw2[j * 32 + k]; }
    for (int i = tid; i < 32;   i += THREADS) s[S_VB2 + i] = vb2[i];
    for (int i = tid; i < 3072; i += THREADS) { int k = i >> 5, j = i & 31; s[S_R1T + i] = rw1[j * 96 + k]; }
    for (int i = tid; i < 32;   i += THREADS) s[S_RB1 + i] = rb1[i];
    for (int i = tid; i < 512;  i += THREADS) { int k = i >> 4, j = i & 15; s[S_R2T + i] = rw2[j * 32 + k]; }
    for (int i = tid; i < 16;   i += THREADS) s[S_RB2 + i] = rb2[i];
    for (int i = tid; i < 48;   i += THREADS) s[S_RW3 + i] = rw3[i];
    for (int i = tid; i < 4;    i += THREADS) s[S_RB3 + i] = (i < 3) ? rb3[i] : 0.f;
    __syncthreads();

    const int p = blockIdx.x * THREADS + tid;
    if (p >= P) return;

    const float* fbase = rgb + (size_t)p * 105;

    // ---- stats pass fused with g1 accumulation (ROLLED: no register-array indexing) ----
    // g1 = bb1 + W1[:, :70] @ [mean(35), var(35)]   (shared across views)
    ull g1[32];
    load_bias<64>(g1, s + S_B1);
#pragma unroll 5
    for (int k = 0; k < 35; ++k) {
        float a = __ldg(fbase + k);
        float b = __ldg(fbase + 35 + k);
        float c = __ldg(fbase + 70 + k);
        if (k < 3) {
            out_in[(size_t)p * 9 + 0 + k] = a;
            out_in[(size_t)p * 9 + 3 + k] = b;
            out_in[(size_t)p * 9 + 6 + k] = c;
        }
        float m  = (a + b + c) * (1.f / 3.f);
        float sq = fmaf(a, a, fmaf(b, b, c * c)) * (1.f / 3.f);
        float q  = fmaf(-m, m, sq);
        fma_row<64>(g1, s + S_W1T + k * 64,        bcast2(m));
        fma_row<64>(g1, s + S_W1T + (35 + k) * 64, bcast2(q));
    }

    // ---- r1 accumulator (final 96->32 layer) ----
    ull r1[16];
    load_bias<32>(r1, s + S_RB1);

    // ---- per-view MLP ----
#pragma unroll 1
    for (int v = 0; v < 3; ++v) {
        const float* fv = fbase + v * 35;

        // h1 = g1 + W1[:, 70:105] @ f_v       (pre-activation, packed)
        ull h1[32];
#pragma unroll
        for (int j = 0; j < 32; ++j) h1[j] = g1[j];
#pragma unroll 5
        for (int k = 0; k < 35; ++k)
            fma_row<64>(h1, s + S_W1T + (70 + k) * 64, bcast2(__ldg(fv + k)));

        // h2 = bb2 + W2 @ elu(h1)             (elu fused at use; h1 dies here)
        ull h2[16];
        load_bias<32>(h2, s + S_B2);
#pragma unroll
        for (int i = 0; i < 32; ++i) {
            float lo, hi; unpack2(h1[i], lo, hi);
            fma_row<32>(h2, s + S_W2T + (2 * i)     * 32, bcast2(elu1(lo)));
            fma_row<32>(h2, s + S_W2T + (2 * i + 1) * 32, bcast2(elu1(hi)));
        }
        // h2e = elu(h2)  (in place — used twice: t1 input and residual)
#pragma unroll
        for (int i = 0; i < 16; ++i) {
            float lo, hi; unpack2(h2[i], lo, hi);
            h2[i] = pack2(elu1(lo), elu1(hi));
        }

        // t1 = vb1 + (vw1/3) @ h2e
        ull t1[16];
        load_bias<32>(t1, s + S_VB1);
#pragma unroll
        for (int i = 0; i < 16; ++i) {
            float lo, hi; unpack2(h2[i], lo, hi);
            fma_row<32>(t1, s + S_V1T + (2 * i)     * 32, bcast2(lo));
            fma_row<32>(t1, s + S_V1T + (2 * i + 1) * 32, bcast2(hi));
        }

        // t2 = vb2 + vw2 @ elu(t1)            (elu fused; t1 dies)
        ull t2[16];
        load_bias<32>(t2, s + S_VB2);
#pragma unroll
        for (int i = 0; i < 16; ++i) {
            float lo, hi; unpack2(t1[i], lo, hi);
            fma_row<32>(t2, s + S_V2T + (2 * i)     * 32, bcast2(elu1(lo)));
            fma_row<32>(t2, s + S_V2T + (2 * i + 1) * 32, bcast2(elu1(hi)));
        }

        // r1 += rw1[:, v*32:(v+1)*32] @ (h2e + elu(t2))   (x computed at use; t2,h2 die)
#pragma unroll
        for (int i = 0; i < 16; ++i) {
            float tlo, thi; unpack2(t2[i], tlo, thi);
            float hlo, hhi; unpack2(h2[i], hlo, hhi);
            fma_row<32>(r1, s + S_R1T + (v * 32 + 2 * i)     * 32, bcast2(hlo + elu1(tlo)));
            fma_row<32>(r1, s + S_R1T + (v * 32 + 2 * i + 1) * 32, bcast2(hhi + elu1(thi)));
        }
    }

    // ---- head: r2 = rb2 + rw2 @ elu(r1) ----
    ull r2[8];
    load_bias<16>(r2, s + S_RB2);
#pragma unroll
    for (int i = 0; i < 16; ++i) {
        float lo, hi; unpack2(r1[i], lo, hi);
        fma_row<16>(r2, s + S_R2T + (2 * i)     * 16, bcast2(elu1(lo)));
        fma_row<16>(r2, s + S_R2T + (2 * i + 1) * 16, bcast2(elu1(hi)));
    }

    // rgb = sigmoid(rb3 + rw3 @ elu(r2))
    float r2e[16];
#pragma unroll
    for (int i = 0; i < 8; ++i) {
        float lo, hi; unpack2(r2[i], lo, hi);
        r2e[2 * i]     = elu1(lo);
        r2e[2 * i + 1] = elu1(hi);
    }
#pragma unroll
    for (int c = 0; c < 3; ++c) {
        float a = s[S_RB3 + c];
#pragma unroll
        for (int k = 0; k < 16; ++k)
            a = fmaf(r2e[k], s[S_RW3 + c * 16 + k], a);
        out_rgb[(size_t)p * 3 + c] = 1.f / (1.f + __expf(-a));
    }
}

extern "C" void kernel_launch(void* const* d_in, const int* in_sizes, int n_in,
                              void* d_out, int out_size)
{
    const float* rgb = (const float*)d_in[0];
    const float* bw1 = (const float*)d_in[1];
    const float* bb1 = (const float*)d_in[2];
    const float* bw2 = (const float*)d_in[3];
    const float* bb2 = (const float*)d_in[4];
    const float* vw1 = (const float*)d_in[5];
    const float* vb1 = (const float*)d_in[6];
    const float* vw2 = (const float*)d_in[7];
    const float* vb2 = (const float*)d_in[8];
    const float* rw1 = (const float*)d_in[9];
    const float* rb1 = (const float*)d_in[10];
    const float* rw2 = (const float*)d_in[11];
    const float* rb2 = (const float*)d_in[12];
    const float* rw3 = (const float*)d_in[13];
    const float* rb3 = (const float*)d_in[14];

    const int P = in_sizes[0] / 105;      // 524288 points
    float* out_in  = (float*)d_out;                   // rgb_in : P*9
    float* out_rgb = (float*)d_out + (size_t)P * 9;   // rgb_out: P*3

    cudaFuncSetAttribute(nerf_rgb_head_kernel,
                         cudaFuncAttributeMaxDynamicSharedMemorySize, SMEM_BYTES);

    const int blocks = (P + THREADS - 1) / THREADS;
    nerf_rgb_head_kernel<<<blocks, THREADS, SMEM_BYTES>>>(
        rgb, bw1, bb1, bw2, bb2, vw1, vb1, vw2, vb2,
        rw1, rb1, rw2, rb2, rw3, rb3, out_in, out_rgb, P);
}

// round 5
// speedup vs baseline: 1.5334x; 1.1008x over previous
#include <cuda_runtime.h>

#define THREADS 256
#define PTS_PER_BLOCK 512   // 2 points per thread

// ---- shared-memory layout (floats) ----
#define S_W1T   0        // [105][64]  bw1 transposed  (6720)
#define S_B1    6720     // [64]
#define S_W2T   6784     // [64][32]   bw2 transposed  (2048)
#define S_B2    8832     // [32]
#define S_V1T   8864     // [32][32]   vw1 transposed, pre-scaled by 1/3 (1024)
#define S_VB1   9888     // [32]
#define S_V2T   9920     // [32][32]   vw2 transposed (1024)
#define S_VB2   10944    // [32]
#define S_R1T   10976    // [96][32]   rw1 transposed (3072)
#define S_RB1   14048    // [32]
#define S_R2T   14080    // [32][16]   rw2 transposed (512)
#define S_RB2   14592    // [16]
#define S_RW3   14608    // [3][16]    rw3 as-is (48)
#define S_RB3   14656    // [4]
#define S_WEND  14660
// g1 buffer: 64 ull slots x 256 threads (A: slots 0..31, B: slots 32..63)
#define S_G1    14660    // 32768 floats
#define S_TOT   (14660 + 32768)
#define SMEM_BYTES (S_TOT * 4)

#define P_CONST 524288

// interleaved input scratch: [P/32][105][32]
__device__ float g_scr[(size_t)P_CONST * 105];

typedef unsigned long long ull;

__device__ __forceinline__ float elu1(float x) {
    return x > 0.f ? x : (__expf(x) - 1.f);
}
__device__ __forceinline__ void ffma2(ull &d, ull a, ull b) {
    asm("fma.rn.f32x2 %0, %1, %2, %0;" : "+l"(d) : "l"(a), "l"(b));
}
__device__ __forceinline__ ull bcast2(float c) {
    ull v; asm("mov.b64 %0, {%1, %2};" : "=l"(v) : "f"(c), "f"(c)); return v;
}
__device__ __forceinline__ ull pack2(float lo, float hi) {
    ull v; asm("mov.b64 %0, {%1, %2};" : "=l"(v) : "f"(lo), "f"(hi)); return v;
}
__device__ __forceinline__ void unpack2(ull v, float &lo, float &hi) {
    asm("mov.b64 {%0, %1}, %2;" : "=f"(lo), "=f"(hi) : "l"(v));
}

// dual-point FMA row: one weight load feeds both points (1 LDS.128 : 4 FFMA2)
template<int OUT>
__device__ __forceinline__ void fma_row2(ull* a, ull* b, const float* row, ull ca, ull cb) {
    const ulonglong2* wp = reinterpret_cast<const ulonglong2*>(row);
#pragma unroll
    for (int q = 0; q < OUT / 4; ++q) {
        ulonglong2 w = wp[q];
        ffma2(a[2 * q],     ca, w.x);
        ffma2(b[2 * q],     cb, w.x);
        ffma2(a[2 * q + 1], ca, w.y);
        ffma2(b[2 * q + 1], cb, w.y);
    }
}
template<int OUT>
__device__ __forceinline__ void load_bias2(ull* a, ull* b, const float* bp_) {
    const ulonglong2* bp = reinterpret_cast<const ulonglong2*>(bp_);
#pragma unroll
    for (int q = 0; q < OUT / 4; ++q) {
        ulonglong2 w = bp[q];
        a[2 * q] = w.x; a[2 * q + 1] = w.y;
        b[2 * q] = w.x; b[2 * q + 1] = w.y;
    }
}

// ================= K0: transpose input to [P/32][105][32] + emit rgb_in ==========
__global__ __launch_bounds__(256, 4)
void k_prep(const float* __restrict__ rgb, float* __restrict__ out_in, int P)
{
    __shared__ float st[32 * 105];
    const int g = blockIdx.x;             // point group (32 points)
    const int tid = threadIdx.x;

    // coalesced read of 32*105 floats (base is 16B-aligned: g*3360*4 = g*13440)
    const float4* src4 = reinterpret_cast<const float4*>(rgb + (size_t)g * 3360);
    float4* st4 = reinterpret_cast<float4*>(st);
#pragma unroll
    for (int i = tid; i < 840; i += 256) st4[i] = src4[i];
    __syncthreads();

    // interleaved write: scr[(g*105 + j)*32 + lane] = st[lane*105 + j]
    float* dst = g_scr + (size_t)g * 105 * 32;
#pragma unroll
    for (int i = tid; i < 3360; i += 256) {
        int j = i >> 5, lane = i & 31;
        dst[i] = st[lane * 105 + j];
    }
    // rgb_in: out_in[p*9 + v*3 + k] = feat[p][v*35 + k], k<3   (288 items, strided!)
    for (int i = tid; i < 288; i += 256) {
        int pl = i / 9, r = i % 9, v = r / 3, k = r % 3;
        out_in[((size_t)g * 32 + pl) * 9 + r] = st[pl * 105 + v * 35 + k];
    }
}

// ================= K1: main fused MLP, 2 points/thread ===========================
__global__ __launch_bounds__(THREADS, 1)
void k_main(
    const float* __restrict__ bw1, const float* __restrict__ bb1,
    const float* __restrict__ bw2, const float* __restrict__ bb2,
    const float* __restrict__ vw1, const float* __restrict__ vb1,
    const float* __restrict__ vw2, const float* __restrict__ vb2,
    const float* __restrict__ rw1, const float* __restrict__ rb1,
    const float* __restrict__ rw2, const float* __restrict__ rb2,
    const float* __restrict__ rw3, const float* __restrict__ rb3,
    float* __restrict__ out_rgb, int P)
{
    extern __shared__ float s[];
    const int tid = threadIdx.x;

    // ---- stage weights (transposed) ----
    for (int i = tid; i < 6720; i += THREADS) { int k = i >> 6, j = i & 63; s[S_W1T + i] = bw1[j * 105 + k]; }
    for (int i = tid; i < 64;   i += THREADS) s[S_B1 + i] = bb1[i];
    for (int i = tid; i < 2048; i += THREADS) { int k = i >> 5, j = i & 31; s[S_W2T + i] = bw2[j * 64 + k]; }
    for (int i = tid; i < 32;   i += THREADS) s[S_B2 + i] = bb2[i];
    for (int i = tid; i < 1024; i += THREADS) { int k = i >> 5, j = i & 31; s[S_V1T + i] = vw1[j * 32 + k] * (1.f / 3.f); }
    for (int i = tid; i < 32;   i += THREADS) s[S_VB1 + i] = vb1[i];
    for (int i = tid; i < 1024; i += THREADS) { int k = i >> 5, j = i & 31; s[S_V2T + i] = vw2[j * 32 + k]; }
    for (int i = tid; i < 32;   i += THREADS) s[S_VB2 + i] = vb2[i];
    for (int i = tid; i < 3072; i += THREADS) { int k = i >> 5, j = i & 31; s[S_R1T + i] = rw1[j * 96 + k]; }
    for (int i = tid; i < 32;   i += THREADS) s[S_RB1 + i] = rb1[i];
    for (int i = tid; i < 512;  i += THREADS) { int k = i >> 4, j = i & 15; s[S_R2T + i] = rw2[j * 32 + k]; }
    for (int i = tid; i < 16;   i += THREADS) s[S_RB2 + i] = rb2[i];
    for (int i = tid; i < 48;   i += THREADS) s[S_RW3 + i] = rw3[i];
    for (int i = tid; i < 4;    i += THREADS) s[S_RB3 + i] = (i < 3) ? rb3[i] : 0.f;
    __syncthreads();

    const int lane = tid & 31;
    const int w    = tid >> 5;
    // point A = blk*512 + tid, point B = A + 256  (P % 512 == 0 for this problem)
    const int p0 = blockIdx.x * PTS_PER_BLOCK + tid;
    const int p1 = p0 + THREADS;
    // interleaved base: element j of point p at scr[(p/32)*105*32 + j*32 + (p%32)]
    const float* fA = g_scr + ((size_t)(blockIdx.x * 16 + w)) * 105 * 32 + lane;
    const float* fB = fA + (size_t)8 * 105 * 32;
#define FA(j) __ldg(fA + (j) * 32)
#define FB(j) __ldg(fB + (j) * 32)

    ull* g1s = reinterpret_cast<ull*>(s + S_G1);

    // ---- phase 1: stats + g1 = bb1 + W1[:,:70] @ [mean,var]  (both points) ----
    {
        ull g1a[32], g1b[32];
        load_bias2<64>(g1a, g1b, s + S_B1);
#pragma unroll 5
        for (int k = 0; k < 35; ++k) {
            float aA = FA(k), bA = FA(35 + k), cA = FA(70 + k);
            float aB = FB(k), bB = FB(35 + k), cB = FB(70 + k);
            float mA = (aA + bA + cA) * (1.f / 3.f);
            float mB = (aB + bB + cB) * (1.f / 3.f);
            float qA = fmaf(-mA, mA, fmaf(aA, aA, fmaf(bA, bA, cA * cA)) * (1.f / 3.f));
            float qB = fmaf(-mB, mB, fmaf(aB, aB, fmaf(bB, bB, cB * cB)) * (1.f / 3.f));
            fma_row2<64>(g1a, g1b, s + S_W1T + k * 64,        bcast2(mA), bcast2(mB));
            fma_row2<64>(g1a, g1b, s + S_W1T + (35 + k) * 64, bcast2(qA), bcast2(qB));
        }
        // park g1 in smem (per-thread slots; conflict-free STS.64)
#pragma unroll
        for (int j = 0; j < 32; ++j) {
            g1s[j * 256 + tid]        = g1a[j];
            g1s[(32 + j) * 256 + tid] = g1b[j];
        }
    }

    // ---- r1 accumulator (96->32 head layer) ----
    ull r1a[16], r1b[16];
    load_bias2<32>(r1a, r1b, s + S_RB1);

    // ---- per-view MLP ----
#pragma unroll 1
    for (int v = 0; v < 3; ++v) {
        ull h2a[16], h2b[16];
        load_bias2<32>(h2a, h2b, s + S_B2);

        // layer1+layer2 in column halves (h = neuron block of 32)
#pragma unroll 1
        for (int h = 0; h < 2; ++h) {
            ull h1a[16], h1b[16];
#pragma unroll
            for (int j = 0; j < 16; ++j) {
                h1a[j] = g1s[(h * 16 + j) * 256 + tid];
                h1b[j] = g1s[(32 + h * 16 + j) * 256 + tid];
            }
#pragma unroll 5
            for (int k = 0; k < 35; ++k) {
                float ca = FA(v * 35 + k), cb = FB(v * 35 + k);
                fma_row2<32>(h1a, h1b, s + S_W1T + (70 + k) * 64 + h * 32,
                             bcast2(ca), bcast2(cb));
            }
            // layer2 partial: rows k2 = h*32 .. h*32+31, consuming elu(h1)
#pragma unroll
            for (int i = 0; i < 16; ++i) {
                float alo, ahi, blo, bhi;
                unpack2(h1a[i], alo, ahi);
                unpack2(h1b[i], blo, bhi);
                fma_row2<32>(h2a, h2b, s + S_W2T + (h * 32 + 2 * i) * 32,
                             bcast2(elu1(alo)), bcast2(elu1(blo)));
                fma_row2<32>(h2a, h2b, s + S_W2T + (h * 32 + 2 * i + 1) * 32,
                             bcast2(elu1(ahi)), bcast2(elu1(bhi)));
            }
        }
        // h2e = elu(h2) in place (used for t1 input AND residual)
#pragma unroll
        for (int i = 0; i < 16; ++i) {
            float lo, hi;
            unpack2(h2a[i], lo, hi); h2a[i] = pack2(elu1(lo), elu1(hi));
            unpack2(h2b[i], lo, hi); h2b[i] = pack2(elu1(lo), elu1(hi));
        }

        // t1 = elu(vb1 + (vw1/3) @ h2e)  (elu applied in place after)
        ull t1a[16], t1b[16];
        load_bias2<32>(t1a, t1b, s + S_VB1);
#pragma unroll
        for (int i = 0; i < 16; ++i) {
            float alo, ahi, blo, bhi;
            unpack2(h2a[i], alo, ahi);
            unpack2(h2b[i], blo, bhi);
            fma_row2<32>(t1a, t1b, s + S_V1T + (2 * i) * 32,     bcast2(alo), bcast2(blo));
            fma_row2<32>(t1a, t1b, s + S_V1T + (2 * i + 1) * 32, bcast2(ahi), bcast2(bhi));
        }
#pragma unroll
        for (int i = 0; i < 16; ++i) {
            float lo, hi;
            unpack2(t1a[i], lo, hi); t1a[i] = pack2(elu1(lo), elu1(hi));
            unpack2(t1b[i], lo, hi); t1b[i] = pack2(elu1(lo), elu1(hi));
        }

        // t2 in quarters of 8 neurons; fold x = h2e + elu(t2) straight into r1
#pragma unroll
        for (int q = 0; q < 4; ++q) {
            ull t2a[4], t2b[4];
            {
                const ulonglong2* bp = reinterpret_cast<const ulonglong2*>(s + S_VB2 + q * 8);
                ulonglong2 b0 = bp[0], b1 = bp[1];
                t2a[0] = b0.x; t2a[1] = b0.y; t2a[2] = b1.x; t2a[3] = b1.y;
                t2b[0] = b0.x; t2b[1] = b0.y; t2b[2] = b1.x; t2b[3] = b1.y;
            }
#pragma unroll
            for (int i = 0; i < 16; ++i) {
                float alo, ahi, blo, bhi;
                unpack2(t1a[i], alo, ahi);
                unpack2(t1b[i], blo, bhi);
                fma_row2<8>(t2a, t2b, s + S_V2T + (2 * i) * 32 + q * 8,     bcast2(alo), bcast2(blo));
                fma_row2<8>(t2a, t2b, s + S_V2T + (2 * i + 1) * 32 + q * 8, bcast2(ahi), bcast2(bhi));
            }
            // x chunk + r1 update
#pragma unroll
            for (int u = 0; u < 4; ++u) {
                float tlo, thi, hlo, hhi;
                unpack2(t2a[u], tlo, thi);
                unpack2(h2a[q * 4 + u], hlo, hhi);
                float xalo = hlo + elu1(tlo), xahi = hhi + elu1(thi);
                unpack2(t2b[u], tlo, thi);
                unpack2(h2b[q * 4 + u], hlo, hhi);
                float xblo = hlo + elu1(tlo), xbhi = hhi + elu1(thi);
                fma_row2<32>(r1a, r1b, s + S_R1T + (v * 32 + q * 8 + 2 * u) * 32,
                             bcast2(xalo), bcast2(xblo));
                fma_row2<32>(r1a, r1b, s + S_R1T + (v * 32 + q * 8 + 2 * u + 1) * 32,
                             bcast2(xahi), bcast2(xbhi));
            }
        }
    }

    // ---- head: r2 = rb2 + rw2 @ elu(r1) ----
    ull r2a[8], r2b[8];
    load_bias2<16>(r2a, r2b, s + S_RB2);
#pragma unroll
    for (int i = 0; i < 16; ++i) {
        float alo, ahi, blo, bhi;
        unpack2(r1a[i], alo, ahi);
        unpack2(r1b[i], blo, bhi);
        fma_row2<16>(r2a, r2b, s + S_R2T + (2 * i) * 16,     bcast2(elu1(alo)), bcast2(elu1(blo)));
        fma_row2<16>(r2a, r2b, s + S_R2T + (2 * i + 1) * 16, bcast2(elu1(ahi)), bcast2(elu1(bhi)));
    }
    float r2eA[16], r2eB[16];
#pragma unroll
    for (int i = 0; i < 8; ++i) {
        float lo, hi;
        unpack2(r2a[i], lo, hi); r2eA[2 * i] = elu1(lo); r2eA[2 * i + 1] = elu1(hi);
        unpack2(r2b[i], lo, hi); r2eB[2 * i] = elu1(lo); r2eB[2 * i + 1] = elu1(hi);
    }
#pragma unroll
    for (int c = 0; c < 3; ++c) {
        float aA = s[S_RB3 + c], aB = aA;
#pragma unroll
        for (int k = 0; k < 16; ++k) {
            float wv = s[S_RW3 + c * 16 + k];
            aA = fmaf(r2eA[k], wv, aA);
            aB = fmaf(r2eB[k], wv, aB);
        }
        out_rgb[(size_t)p0 * 3 + c] = 1.f / (1.f + __expf(-aA));
        out_rgb[(size_t)p1 * 3 + c] = 1.f / (1.f + __expf(-aB));
    }
#undef FA
#undef FB
}

extern "C" void kernel_launch(void* const* d_in, const int* in_sizes, int n_in,
                              void* d_out, int out_size)
{
    const float* rgb = (const float*)d_in[0];
    const float* bw1 = (const float*)d_in[1];
    const float* bb1 = (const float*)d_in[2];
    const float* bw2 = (const float*)d_in[3];
    const float* bb2 = (const float*)d_in[4];
    const float* vw1 = (const float*)d_in[5];
    const float* vb1 = (const float*)d_in[6];
    const float* vw2 = (const float*)d_in[7];
    const float* vb2 = (const float*)d_in[8];
    const float* rw1 = (const float*)d_in[9];
    const float* rb1 = (const float*)d_in[10];
    const float* rw2 = (const float*)d_in[11];
    const float* rb2 = (const float*)d_in[12];
    const float* rw3 = (const float*)d_in[13];
    const float* rb3 = (const float*)d_in[14];

    const int P = in_sizes[0] / 105;                  // 524288
    float* out_in  = (float*)d_out;                   // rgb_in : P*9
    float* out_rgb = (float*)d_out + (size_t)P * 9;   // rgb_out: P*3

    // K0: input transpose + rgb_in
    k_prep<<<P / 32, 256>>>(rgb, out_in, P);

    // K1: fused MLP
    cudaFuncSetAttribute(k_main, cudaFuncAttributeMaxDynamicSharedMemorySize, SMEM_BYTES);
    k_main<<<P / PTS_PER_BLOCK, THREADS, SMEM_BYTES>>>(
        bw1, bb1, bw2, bb2, vw1, vb1, vw2, vb2,
        rw1, rb1, rw2, rb2, rw3, rb3, out_rgb, P);
}